// round 12
// baseline (speedup 1.0000x reference)
#include <cuda_runtime.h>
#include <cuda_bf16.h>
#include <math.h>

// inputs: x[f32] (unused), src[i32 E], dst[i32 E], path_len[i32 E], b[f32 5].
// output: f32 N*N.  out = zeros; out[src[i],dst[i]] = b[min(plen[i],5)-1],
// LAST duplicate (highest i) wins.
//
// Multisplit row-binning, no global atomics:
//   H2 : per-CTA smem histogram of src -> g_cnt[cta][row]   (coalesced)
//   K1 : segment sums over cta axis (8 segs x 32) -> g_seg[seg][row]
//   K2 : per-row totals + exclusive scan over rows -> g_rowStart/g_total,
//        plus per-(seg,row) bases -> g_segstart  (g_seg re-read, low regs)
//   K3 : each (seg,row): batch-load 32 counts, local prefix, write absolute
//        offsets back into g_cnt (in place)
//   B2 : per-CTA smem cursors (coalesced reload); slot = smem atomicAdd ->
//        g_bins[slot] = {key, dst}
//   AP : one CTA per row: smem atomicMax(tile[dst], key) (key monotone in
//        pair index i resolves last-write-wins), dense coalesced row store.

#ifndef MAX_PATH_DISTANCE
#define MAX_PATH_DISTANCE 5
#endif

#define N_MAX 8192
#define E_MAX (4 * 1024 * 1024)
#define NCTA  256
#define NSEG  8
#define SEGW  (NCTA / NSEG)          // 32

__device__ int  g_cnt[NCTA * N_MAX];     // [cta][row], 8 MB
__device__ int  g_seg[NSEG * N_MAX];     // [seg][row]
__device__ int  g_segstart[NSEG * N_MAX];
__device__ int  g_total[N_MAX];
__device__ int  g_rowStart[N_MAX];
__device__ int2 g_bins[E_MAX];           // 32 MB

// ---------------- H2: per-CTA smem histogram ----------------
__global__ void __launch_bounds__(256) hist2_kernel(const int* __restrict__ src,
                                                    int n_pairs, int chunk) {
    __shared__ int cnt[N_MAX];
    int t = threadIdx.x, nt = blockDim.x, c = blockIdx.x;
    for (int i = t; i < N_MAX; i += nt) cnt[i] = 0;
    __syncthreads();

    int begin = c * chunk;                       // chunk is a multiple of 4
    int end = min(begin + chunk, n_pairs);
    int nfull = begin + ((end - begin) & ~3);

    for (int base = begin + t * 4; base < nfull; base += nt * 4) {
        int4 s = *reinterpret_cast<const int4*>(src + base);
        atomicAdd(&cnt[s.x], 1); atomicAdd(&cnt[s.y], 1);
        atomicAdd(&cnt[s.z], 1); atomicAdd(&cnt[s.w], 1);
    }
    for (int k = nfull + t; k < end; k += nt) atomicAdd(&cnt[src[k]], 1);
    __syncthreads();

    for (int i = t; i < N_MAX; i += nt)
        g_cnt[c * N_MAX + i] = cnt[i];           // coalesced
}

// ---------------- K1: segment sums over the cta axis ----------------
__global__ void __launch_bounds__(256) segsum_kernel() {
    int t = blockIdx.x * blockDim.x + threadIdx.x;   // t = seg*N_MAX + row
    if (t >= NSEG * N_MAX) return;
    int seg = t >> 13;                // / N_MAX
    int row = t & (N_MAX - 1);
    int sum = 0;
#pragma unroll
    for (int j = 0; j < SEGW; ++j)
        sum += g_cnt[(seg * SEGW + j) * N_MAX + row];   // coalesced across lanes
    g_seg[seg * N_MAX + row] = sum;
}

// ---------------- K2: totals + row scan + segment bases ----------------
__global__ void __launch_bounds__(1024) scan_kernel(int n) {
    __shared__ int sdata[1024];
    int t = threadIdx.x;

    int rowtot[8];
    int sum = 0;
#pragma unroll
    for (int j = 0; j < 8; ++j) {
        int r = t * 8 + j;
        int s = 0;
#pragma unroll
        for (int k = 0; k < NSEG; ++k)
            s += g_seg[k * N_MAX + r];
        rowtot[j] = s;
        sum += s;
    }
    sdata[t] = sum;
    __syncthreads();
    for (int off = 1; off < 1024; off <<= 1) {
        int v = (t >= off) ? sdata[t - off] : 0;
        __syncthreads();
        sdata[t] += v;
        __syncthreads();
    }
    int run = sdata[t] - sum;                    // exclusive prefix over rows
#pragma unroll
    for (int j = 0; j < 8; ++j) {
        int r = t * 8 + j;
        g_rowStart[r] = run;
        g_total[r]   = rowtot[j];
        int sb = run;
#pragma unroll
        for (int k = 0; k < NSEG; ++k) {
            g_segstart[k * N_MAX + r] = sb;
            sb += g_seg[k * N_MAX + r];          // re-read, L2/L1-hot
        }
        run += rowtot[j];
    }
}

// ---------------- K3: counts -> absolute offsets (in place) ----------------
__global__ void __launch_bounds__(256) offsets_kernel() {
    int t = blockIdx.x * blockDim.x + threadIdx.x;   // t = seg*N_MAX + row
    if (t >= NSEG * N_MAX) return;
    int seg = t >> 13;
    int row = t & (N_MAX - 1);

    int v[SEGW];
#pragma unroll
    for (int j = 0; j < SEGW; ++j)                   // independent loads, MLP 32
        v[j] = g_cnt[(seg * SEGW + j) * N_MAX + row];

    int run = g_segstart[seg * N_MAX + row];
#pragma unroll
    for (int j = 0; j < SEGW; ++j) {
        g_cnt[(seg * SEGW + j) * N_MAX + row] = run;
        run += v[j];
    }
}

// ---------------- B2: place pairs via smem cursors ----------------
__global__ void __launch_bounds__(256) bin2_kernel(const int* __restrict__ src,
                                                   const int* __restrict__ dst,
                                                   const int* __restrict__ plen,
                                                   int n_pairs, int chunk) {
    __shared__ int cur[N_MAX];
    int t = threadIdx.x, nt = blockDim.x, c = blockIdx.x;
    for (int i = t; i < N_MAX; i += nt) cur[i] = g_cnt[c * N_MAX + i];  // coalesced
    __syncthreads();

    int begin = c * chunk;
    int end = min(begin + chunk, n_pairs);
    int nfull = begin + ((end - begin) & ~3);

    for (int base = begin + t * 4; base < nfull; base += nt * 4) {
        int4 s = *reinterpret_cast<const int4*>(src + base);
        int4 d = *reinterpret_cast<const int4*>(dst + base);
        int4 p = *reinterpret_cast<const int4*>(plen + base);
        int ss[4] = {s.x, s.y, s.z, s.w};
        int dd[4] = {d.x, d.y, d.z, d.w};
        int pp[4] = {p.x, p.y, p.z, p.w};
#pragma unroll
        for (int j = 0; j < 4; ++j) {
            int idx = min(pp[j], MAX_PATH_DISTANCE) - 1;     // 0..4
            int key = ((base + j + 1) << 3) | idx;           // >0, monotone in i
            int slot = atomicAdd(&cur[ss[j]], 1);
            g_bins[slot] = make_int2(key, dd[j]);
        }
    }
    for (int k = nfull + t; k < end; k += nt) {
        int idx = min(plen[k], MAX_PATH_DISTANCE) - 1;
        int key = ((k + 1) << 3) | idx;
        int slot = atomicAdd(&cur[src[k]], 1);
        g_bins[slot] = make_int2(key, dst[k]);
    }
}

// ---------------- AP: per-row resolve + dense write ----------------
__global__ void __launch_bounds__(512) apply_kernel(float* __restrict__ out,
                                                    const float* __restrict__ b,
                                                    int n_nodes) {
    __shared__ int row[N_MAX];
    __shared__ float bs[8];

    int r = blockIdx.x;
    int t = threadIdx.x;
    int nt = blockDim.x;

    int n4 = n_nodes >> 2;
    int4 z4 = make_int4(0, 0, 0, 0);
    for (int i = t; i < n4; i += nt)
        reinterpret_cast<int4*>(row)[i] = z4;
    if (t < 8) bs[t] = b[min(t, MAX_PATH_DISTANCE - 1)];
    __syncthreads();

    int begin = g_rowStart[r];
    int end   = begin + g_total[r];

    for (int i = begin + t; i < end; i += nt) {
        int2 e = g_bins[i];                      // coalesced segment read
        atomicMax(&row[e.y], e.x);               // spread smem atomics
    }
    __syncthreads();

    float* orow = out + (size_t)r * n_nodes;
    for (int i = t; i < n4; i += nt) {
        int4 v = reinterpret_cast<const int4*>(row)[i];
        float4 o;
        o.x = v.x ? bs[v.x & 7] : 0.0f;
        o.y = v.y ? bs[v.y & 7] : 0.0f;
        o.z = v.z ? bs[v.z & 7] : 0.0f;
        o.w = v.w ? bs[v.w & 7] : 0.0f;
        reinterpret_cast<float4*>(orow)[i] = o;
    }
}

extern "C" void kernel_launch(void* const* d_in, const int* in_sizes, int n_in,
                              void* d_out, int out_size) {
    const int* src  = (const int*)d_in[1];
    const int* dst  = (const int*)d_in[2];
    const int* plen = (const int*)d_in[3];
    const float* b  = (const float*)d_in[4];

    int n_pairs = in_sizes[1];
    int n_nodes = (int)llround(sqrt((double)out_size));
    float* out = (float*)d_out;

    int chunk = (n_pairs + NCTA - 1) / NCTA;
    chunk = (chunk + 3) & ~3;                    // 4-aligned chunks for int4

    hist2_kernel<<<NCTA, 256>>>(src, n_pairs, chunk);
    segsum_kernel<<<(NSEG * N_MAX) / 256, 256>>>();
    scan_kernel<<<1, 1024>>>(n_nodes);
    offsets_kernel<<<(NSEG * N_MAX) / 256, 256>>>();
    bin2_kernel<<<NCTA, 256>>>(src, dst, plen, n_pairs, chunk);
    apply_kernel<<<n_nodes, 512>>>(out, b, n_nodes);
}

// round 13
// speedup vs baseline: 1.0305x; 1.0305x over previous
#include <cuda_runtime.h>
#include <cuda_bf16.h>
#include <math.h>

// inputs: x[f32] (unused), src[i32 E], dst[i32 E], path_len[i32 E], b[f32 5].
// output: f32 N*N.  out = zeros; out[src[i],dst[i]] = b[min(plen[i],5)-1],
// LAST duplicate (highest i) wins.
//
// Multisplit row-binning, no global atomics:
//   H2 : per-CTA smem histogram of src -> g_cnt[cta][row]   (coalesced)
//   K1 : segment sums over cta axis (8 segs x 32) -> g_seg[seg][row]
//   K2 : per-row totals + exclusive scan over rows -> g_rowStart/g_total,
//        plus per-(seg,row) bases -> g_segstart
//   K3 : each (seg,row): batch-load 32 counts, local prefix, write absolute
//        offsets back into g_cnt (in place)
//   B2 : per-CTA smem cursors (coalesced reload); slot = smem atomicAdd ->
//        g_bins[slot] = {key, dst}
//   AP : one CTA per row (256 thr, as in the 154.6us best): smem
//        atomicMax(tile[dst], key) (key monotone in pair index i), dense
//        coalesced row store.

#ifndef MAX_PATH_DISTANCE
#define MAX_PATH_DISTANCE 5
#endif

#define N_MAX 8192
#define E_MAX (4 * 1024 * 1024)
#define NCTA  256
#define NSEG  8
#define SEGW  (NCTA / NSEG)          // 32

__device__ int  g_cnt[NCTA * N_MAX];     // [cta][row], 8 MB
__device__ int  g_seg[NSEG * N_MAX];     // [seg][row]
__device__ int  g_segstart[NSEG * N_MAX];
__device__ int  g_total[N_MAX];
__device__ int  g_rowStart[N_MAX];
__device__ int2 g_bins[E_MAX];           // 32 MB

// ---------------- H2: per-CTA smem histogram ----------------
__global__ void __launch_bounds__(256) hist2_kernel(const int* __restrict__ src,
                                                    int n_pairs, int chunk) {
    __shared__ int cnt[N_MAX];
    int t = threadIdx.x, nt = blockDim.x, c = blockIdx.x;
    for (int i = t; i < N_MAX; i += nt) cnt[i] = 0;
    __syncthreads();

    int begin = c * chunk;                       // chunk is a multiple of 4
    int end = min(begin + chunk, n_pairs);
    int nfull = begin + ((end - begin) & ~3);

    for (int base = begin + t * 4; base < nfull; base += nt * 4) {
        int4 s = *reinterpret_cast<const int4*>(src + base);
        atomicAdd(&cnt[s.x], 1); atomicAdd(&cnt[s.y], 1);
        atomicAdd(&cnt[s.z], 1); atomicAdd(&cnt[s.w], 1);
    }
    for (int k = nfull + t; k < end; k += nt) atomicAdd(&cnt[src[k]], 1);
    __syncthreads();

    for (int i = t; i < N_MAX; i += nt)
        g_cnt[c * N_MAX + i] = cnt[i];           // coalesced
}

// ---------------- K1: segment sums over the cta axis ----------------
__global__ void __launch_bounds__(256) segsum_kernel() {
    int t = blockIdx.x * blockDim.x + threadIdx.x;   // t = seg*N_MAX + row
    if (t >= NSEG * N_MAX) return;
    int seg = t >> 13;                // / N_MAX
    int row = t & (N_MAX - 1);
    int sum = 0;
#pragma unroll
    for (int j = 0; j < SEGW; ++j)
        sum += g_cnt[(seg * SEGW + j) * N_MAX + row];   // coalesced across lanes
    g_seg[seg * N_MAX + row] = sum;
}

// ---------------- K2: totals + row scan + segment bases ----------------
__global__ void __launch_bounds__(1024) scan_kernel(int n) {
    __shared__ int sdata[1024];
    int t = threadIdx.x;

    int rowtot[8];
    int sum = 0;
#pragma unroll
    for (int j = 0; j < 8; ++j) {
        int r = t * 8 + j;
        int s = 0;
#pragma unroll
        for (int k = 0; k < NSEG; ++k)
            s += g_seg[k * N_MAX + r];
        rowtot[j] = s;
        sum += s;
    }
    sdata[t] = sum;
    __syncthreads();
    for (int off = 1; off < 1024; off <<= 1) {
        int v = (t >= off) ? sdata[t - off] : 0;
        __syncthreads();
        sdata[t] += v;
        __syncthreads();
    }
    int run = sdata[t] - sum;                    // exclusive prefix over rows
#pragma unroll
    for (int j = 0; j < 8; ++j) {
        int r = t * 8 + j;
        g_rowStart[r] = run;
        g_total[r]   = rowtot[j];
        int sb = run;
#pragma unroll
        for (int k = 0; k < NSEG; ++k) {
            g_segstart[k * N_MAX + r] = sb;
            sb += g_seg[k * N_MAX + r];          // re-read, L2/L1-hot
        }
        run += rowtot[j];
    }
}

// ---------------- K3: counts -> absolute offsets (in place) ----------------
__global__ void __launch_bounds__(256) offsets_kernel() {
    int t = blockIdx.x * blockDim.x + threadIdx.x;   // t = seg*N_MAX + row
    if (t >= NSEG * N_MAX) return;
    int seg = t >> 13;
    int row = t & (N_MAX - 1);

    int v[SEGW];
#pragma unroll
    for (int j = 0; j < SEGW; ++j)                   // independent loads, MLP 32
        v[j] = g_cnt[(seg * SEGW + j) * N_MAX + row];

    int run = g_segstart[seg * N_MAX + row];
#pragma unroll
    for (int j = 0; j < SEGW; ++j) {
        g_cnt[(seg * SEGW + j) * N_MAX + row] = run;
        run += v[j];
    }
}

// ---------------- B2: place pairs via smem cursors ----------------
__global__ void __launch_bounds__(256) bin2_kernel(const int* __restrict__ src,
                                                   const int* __restrict__ dst,
                                                   const int* __restrict__ plen,
                                                   int n_pairs, int chunk) {
    __shared__ int cur[N_MAX];
    int t = threadIdx.x, nt = blockDim.x, c = blockIdx.x;
    for (int i = t; i < N_MAX; i += nt) cur[i] = g_cnt[c * N_MAX + i];  // coalesced
    __syncthreads();

    int begin = c * chunk;
    int end = min(begin + chunk, n_pairs);
    int nfull = begin + ((end - begin) & ~3);

    for (int base = begin + t * 4; base < nfull; base += nt * 4) {
        int4 s = *reinterpret_cast<const int4*>(src + base);
        int4 d = *reinterpret_cast<const int4*>(dst + base);
        int4 p = *reinterpret_cast<const int4*>(plen + base);
        int ss[4] = {s.x, s.y, s.z, s.w};
        int dd[4] = {d.x, d.y, d.z, d.w};
        int pp[4] = {p.x, p.y, p.z, p.w};
#pragma unroll
        for (int j = 0; j < 4; ++j) {
            int idx = min(pp[j], MAX_PATH_DISTANCE) - 1;     // 0..4
            int key = ((base + j + 1) << 3) | idx;           // >0, monotone in i
            int slot = atomicAdd(&cur[ss[j]], 1);
            g_bins[slot] = make_int2(key, dd[j]);
        }
    }
    for (int k = nfull + t; k < end; k += nt) {
        int idx = min(plen[k], MAX_PATH_DISTANCE) - 1;
        int key = ((k + 1) << 3) | idx;
        int slot = atomicAdd(&cur[src[k]], 1);
        g_bins[slot] = make_int2(key, dst[k]);
    }
}

// ---------------- AP: per-row resolve + dense write (R8 version, 256 thr) ----
__global__ void __launch_bounds__(256) apply_kernel(float* __restrict__ out,
                                                    const float* __restrict__ b,
                                                    int n_nodes) {
    __shared__ int row[N_MAX];
    __shared__ float bs[8];

    int r = blockIdx.x;
    int t = threadIdx.x;
    int nt = blockDim.x;

    int n4 = n_nodes >> 2;
    int4 z4 = make_int4(0, 0, 0, 0);
    for (int i = t; i < n4; i += nt)
        reinterpret_cast<int4*>(row)[i] = z4;
    if (t < 8) bs[t] = b[min(t, MAX_PATH_DISTANCE - 1)];
    __syncthreads();

    int begin = g_rowStart[r];
    int end   = begin + g_total[r];

    for (int i = begin + t; i < end; i += nt) {
        int2 e = g_bins[i];                      // coalesced segment read
        atomicMax(&row[e.y], e.x);               // spread smem atomics
    }
    __syncthreads();

    float* orow = out + (size_t)r * n_nodes;
    for (int i = t; i < n4; i += nt) {
        int4 v = reinterpret_cast<const int4*>(row)[i];
        float4 o;
        o.x = v.x ? bs[v.x & 7] : 0.0f;
        o.y = v.y ? bs[v.y & 7] : 0.0f;
        o.z = v.z ? bs[v.z & 7] : 0.0f;
        o.w = v.w ? bs[v.w & 7] : 0.0f;
        reinterpret_cast<float4*>(orow)[i] = o;
    }
}

extern "C" void kernel_launch(void* const* d_in, const int* in_sizes, int n_in,
                              void* d_out, int out_size) {
    const int* src  = (const int*)d_in[1];
    const int* dst  = (const int*)d_in[2];
    const int* plen = (const int*)d_in[3];
    const float* b  = (const float*)d_in[4];

    int n_pairs = in_sizes[1];
    int n_nodes = (int)llround(sqrt((double)out_size));
    float* out = (float*)d_out;

    int chunk = (n_pairs + NCTA - 1) / NCTA;
    chunk = (chunk + 3) & ~3;                    // 4-aligned chunks for int4

    hist2_kernel<<<NCTA, 256>>>(src, n_pairs, chunk);
    segsum_kernel<<<(NSEG * N_MAX) / 256, 256>>>();
    scan_kernel<<<1, 1024>>>(n_nodes);
    offsets_kernel<<<(NSEG * N_MAX) / 256, 256>>>();
    bin2_kernel<<<NCTA, 256>>>(src, dst, plen, n_pairs, chunk);
    apply_kernel<<<n_nodes, 256>>>(out, b, n_nodes);
}

// round 14
// speedup vs baseline: 1.3199x; 1.2807x over previous
#include <cuda_runtime.h>
#include <math.h>

// inputs: x[f32] (unused), src[i32 E], dst[i32 E], path_len[i32 E], b[f32 5].
// output: f32 N*N.  out = zeros; out[src[i],dst[i]] = b[min(plen[i],5)-1],
// LAST duplicate (highest i) wins.
//
// Multisplit row-binning, no global atomics. NCTA=1024 so the pair passes run
// at ~87% occupancy (256 CTAs was 22% -- they are latency chains, not BW).
//   H2 : per-CTA smem histogram of src -> g_cnt[cta][row]  (coalesced, 32 MB)
//   K1 : segment sums over cta axis (32 segs x 32) -> g_seg[seg][row]
//   K1b: per-row totals from g_seg -> g_total       (coalesced, parallel)
//   K2 : 1-CTA exclusive scan of g_total (32 KB only) -> g_rowStart
//   K2b: per-row running bases over segs -> g_segstart (parallel)
//   K3 : per-(seg,row): batch-load 32 counts, local prefix -> absolute
//        offsets back into g_cnt (in place)
//   B2 : per-CTA smem cursors; slot = smem atomicAdd -> g_bins[slot]={key,dst}
//   AP : one CTA per row: smem atomicMax(tile[dst], key) (key monotone in
//        pair index i), dense coalesced row store (__stcs streaming).

#ifndef MAX_PATH_DISTANCE
#define MAX_PATH_DISTANCE 5
#endif

#define N_MAX 8192
#define E_MAX (4 * 1024 * 1024)
#define NCTA  1024
#define NSEG  32
#define SEGW  (NCTA / NSEG)          // 32

__device__ int  g_cnt[NCTA * N_MAX];     // [cta][row], 32 MB
__device__ int  g_seg[NSEG * N_MAX];     // [seg][row], 1 MB
__device__ int  g_segstart[NSEG * N_MAX];
__device__ int  g_total[N_MAX];
__device__ int  g_rowStart[N_MAX];
__device__ int2 g_bins[E_MAX];           // 32 MB

// ---------------- H2: per-CTA smem histogram ----------------
__global__ void __launch_bounds__(256) hist2_kernel(const int* __restrict__ src,
                                                    int n_pairs, int chunk) {
    __shared__ int cnt[N_MAX];
    int t = threadIdx.x, nt = blockDim.x, c = blockIdx.x;
    for (int i = t; i < N_MAX; i += nt) cnt[i] = 0;
    __syncthreads();

    int begin = c * chunk;                       // chunk is a multiple of 4
    int end = min(begin + chunk, n_pairs);
    if (begin < end) {
        int nfull = begin + ((end - begin) & ~3);
        for (int base = begin + t * 4; base < nfull; base += nt * 4) {
            int4 s = *reinterpret_cast<const int4*>(src + base);
            atomicAdd(&cnt[s.x], 1); atomicAdd(&cnt[s.y], 1);
            atomicAdd(&cnt[s.z], 1); atomicAdd(&cnt[s.w], 1);
        }
        for (int k = nfull + t; k < end; k += nt) atomicAdd(&cnt[src[k]], 1);
    }
    __syncthreads();

    for (int i = t; i < N_MAX; i += nt)
        g_cnt[c * N_MAX + i] = cnt[i];           // coalesced
}

// ---------------- K1: segment sums over the cta axis ----------------
__global__ void __launch_bounds__(256) segsum_kernel() {
    int t = blockIdx.x * blockDim.x + threadIdx.x;   // t = seg*N_MAX + row
    if (t >= NSEG * N_MAX) return;
    int seg = t >> 13;                // / N_MAX
    int row = t & (N_MAX - 1);
    int sum = 0;
#pragma unroll
    for (int j = 0; j < SEGW; ++j)
        sum += g_cnt[(seg * SEGW + j) * N_MAX + row];   // coalesced across lanes
    g_seg[seg * N_MAX + row] = sum;
}

// ---------------- K1b: per-row totals ----------------
__global__ void __launch_bounds__(256) rowtot_kernel() {
    int row = blockIdx.x * blockDim.x + threadIdx.x;
    if (row >= N_MAX) return;
    int sum = 0;
#pragma unroll
    for (int k = 0; k < NSEG; ++k)
        sum += g_seg[k * N_MAX + row];           // coalesced across lanes
    g_total[row] = sum;
}

// ---------------- K2: exclusive scan of totals (32 KB only) ----------------
__global__ void __launch_bounds__(1024) scan_kernel(int n) {
    __shared__ int sdata[1024];
    int t = threadIdx.x;

    int vals[8];
    int sum = 0;
#pragma unroll
    for (int j = 0; j < 8; ++j) {
        int r = t * 8 + j;
        vals[j] = (r < n) ? g_total[r] : 0;
        sum += vals[j];
    }
    sdata[t] = sum;
    __syncthreads();
    for (int off = 1; off < 1024; off <<= 1) {
        int v = (t >= off) ? sdata[t - off] : 0;
        __syncthreads();
        sdata[t] += v;
        __syncthreads();
    }
    int run = sdata[t] - sum;                    // exclusive prefix over rows
#pragma unroll
    for (int j = 0; j < 8; ++j) {
        int r = t * 8 + j;
        if (r < n) g_rowStart[r] = run;
        run += vals[j];
    }
}

// ---------------- K2b: per-(seg,row) bases ----------------
__global__ void __launch_bounds__(256) segstart_kernel() {
    int row = blockIdx.x * blockDim.x + threadIdx.x;
    if (row >= N_MAX) return;
    int run = g_rowStart[row];
#pragma unroll
    for (int k = 0; k < NSEG; ++k) {
        g_segstart[k * N_MAX + row] = run;       // coalesced
        run += g_seg[k * N_MAX + row];
    }
}

// ---------------- K3: counts -> absolute offsets (in place) ----------------
__global__ void __launch_bounds__(256) offsets_kernel() {
    int t = blockIdx.x * blockDim.x + threadIdx.x;   // t = seg*N_MAX + row
    if (t >= NSEG * N_MAX) return;
    int seg = t >> 13;
    int row = t & (N_MAX - 1);

    int v[SEGW];
#pragma unroll
    for (int j = 0; j < SEGW; ++j)                   // independent loads, MLP 32
        v[j] = g_cnt[(seg * SEGW + j) * N_MAX + row];

    int run = g_segstart[seg * N_MAX + row];
#pragma unroll
    for (int j = 0; j < SEGW; ++j) {
        g_cnt[(seg * SEGW + j) * N_MAX + row] = run;
        run += v[j];
    }
}

// ---------------- B2: place pairs via smem cursors ----------------
__global__ void __launch_bounds__(256) bin2_kernel(const int* __restrict__ src,
                                                   const int* __restrict__ dst,
                                                   const int* __restrict__ plen,
                                                   int n_pairs, int chunk) {
    __shared__ int cur[N_MAX];
    int t = threadIdx.x, nt = blockDim.x, c = blockIdx.x;
    for (int i = t; i < N_MAX; i += nt) cur[i] = g_cnt[c * N_MAX + i];  // coalesced
    __syncthreads();

    int begin = c * chunk;
    int end = min(begin + chunk, n_pairs);
    if (begin < end) {
        int nfull = begin + ((end - begin) & ~3);

        for (int base = begin + t * 4; base < nfull; base += nt * 4) {
            int4 s = *reinterpret_cast<const int4*>(src + base);
            int4 d = *reinterpret_cast<const int4*>(dst + base);
            int4 p = *reinterpret_cast<const int4*>(plen + base);
            int ss[4] = {s.x, s.y, s.z, s.w};
            int dd[4] = {d.x, d.y, d.z, d.w};
            int pp[4] = {p.x, p.y, p.z, p.w};
#pragma unroll
            for (int j = 0; j < 4; ++j) {
                int idx = min(pp[j], MAX_PATH_DISTANCE) - 1;     // 0..4
                int key = ((base + j + 1) << 3) | idx;           // >0, monotone in i
                int slot = atomicAdd(&cur[ss[j]], 1);
                g_bins[slot] = make_int2(key, dd[j]);
            }
        }
        for (int k = nfull + t; k < end; k += nt) {
            int idx = min(plen[k], MAX_PATH_DISTANCE) - 1;
            int key = ((k + 1) << 3) | idx;
            int slot = atomicAdd(&cur[src[k]], 1);
            g_bins[slot] = make_int2(key, dst[k]);
        }
    }
}

// ---------------- AP: per-row resolve + dense streaming write ----------------
__global__ void __launch_bounds__(256) apply_kernel(float* __restrict__ out,
                                                    const float* __restrict__ b,
                                                    int n_nodes) {
    __shared__ int row[N_MAX];
    __shared__ float bs[8];

    int r = blockIdx.x;
    int t = threadIdx.x;
    int nt = blockDim.x;

    int n4 = n_nodes >> 2;
    int4 z4 = make_int4(0, 0, 0, 0);
    for (int i = t; i < n4; i += nt)
        reinterpret_cast<int4*>(row)[i] = z4;
    if (t < 8) bs[t] = b[min(t, MAX_PATH_DISTANCE - 1)];
    __syncthreads();

    int begin = g_rowStart[r];
    int end   = begin + g_total[r];

    for (int i = begin + t; i < end; i += nt) {
        int2 e = __ldcs(&g_bins[i]);             // streaming: no reuse after
        atomicMax(&row[e.y], e.x);               // spread smem atomics
    }
    __syncthreads();

    float* orow = out + (size_t)r * n_nodes;
    for (int i = t; i < n4; i += nt) {
        int4 v = reinterpret_cast<const int4*>(row)[i];
        float4 o;
        o.x = v.x ? bs[v.x & 7] : 0.0f;
        o.y = v.y ? bs[v.y & 7] : 0.0f;
        o.z = v.z ? bs[v.z & 7] : 0.0f;
        o.w = v.w ? bs[v.w & 7] : 0.0f;
        __stcs(reinterpret_cast<float4*>(orow) + i, o);  // streaming store
    }
}

extern "C" void kernel_launch(void* const* d_in, const int* in_sizes, int n_in,
                              void* d_out, int out_size) {
    const int* src  = (const int*)d_in[1];
    const int* dst  = (const int*)d_in[2];
    const int* plen = (const int*)d_in[3];
    const float* b  = (const float*)d_in[4];

    int n_pairs = in_sizes[1];
    int n_nodes = (int)llround(sqrt((double)out_size));
    float* out = (float*)d_out;

    int chunk = (n_pairs + NCTA - 1) / NCTA;
    chunk = (chunk + 3) & ~3;                    // 4-aligned chunks for int4

    hist2_kernel<<<NCTA, 256>>>(src, n_pairs, chunk);
    segsum_kernel<<<(NSEG * N_MAX) / 256, 256>>>();
    rowtot_kernel<<<N_MAX / 256, 256>>>();
    scan_kernel<<<1, 1024>>>(n_nodes);
    segstart_kernel<<<N_MAX / 256, 256>>>();
    offsets_kernel<<<(NSEG * N_MAX) / 256, 256>>>();
    bin2_kernel<<<NCTA, 256>>>(src, dst, plen, n_pairs, chunk);
    apply_kernel<<<n_nodes, 256>>>(out, b, n_nodes);
}